// round 17
// baseline (speedup 1.0000x reference)
#include <cuda_runtime.h>
#include <cuda_fp16.h>
#include <math.h>
#include <stdint.h>

#define B_   4
#define L_   2048
#define DX_  1024
#define H_   16
#define DK_  64
#define HD_  1024      // H*DK
#define EPS_ 1e-5f

// ---------------- scratch (device globals; no allocation allowed) ----------------
__device__ __half g_Qs[(size_t)B_ * L_ * HD_];
__device__ __half g_Ks[(size_t)B_ * L_ * HD_];
__device__ __half g_Vs[(size_t)B_ * L_ * HD_];
__device__ __half g_VsT[(size_t)B_ * H_ * DK_ * L_];  // [bh*64+d][l]
__device__ float g_AO[(size_t)B_ * L_ * HD_];
__device__ float g_X [(size_t)B_ * L_ * DX_];
__device__ float g_rWq[(size_t)DX_ * HD_];   // tf32-rounded weights, [K][N] layout
__device__ float g_rWk[(size_t)DX_ * HD_];
__device__ float g_rWv[(size_t)DX_ * HD_];
__device__ float g_rWo[(size_t)HD_ * DX_];
__device__ float g_invS[(size_t)B_ * H_ * L_];  // (b*16+h, row): 1/rowsum

// ---------------- helpers ---------------------------------------------------------
__device__ __forceinline__ unsigned f2tf(float x) {
    unsigned r; asm("cvt.rna.tf32.f32 %0, %1;" : "=r"(r) : "f"(x)); return r;
}
__device__ __forceinline__ float rndtf(float x) { return __uint_as_float(f2tf(x)); }

__device__ __forceinline__ void cp16(void* s, const void* g) {
    unsigned a = (unsigned)__cvta_generic_to_shared(s);
    asm volatile("cp.async.cg.shared.global [%0], [%1], 16;" :: "r"(a), "l"(g));
}
__device__ __forceinline__ void cpcommit() {
    asm volatile("cp.async.commit_group;" ::: "memory");
}
__device__ __forceinline__ void cpwait0() {
    asm volatile("cp.async.wait_group 0;" ::: "memory");
}
__device__ __forceinline__ void cpwait1() {
    asm volatile("cp.async.wait_group 1;" ::: "memory");
}
__device__ __forceinline__ void stg_cs4(float* g, float4 v) {
    asm volatile("st.global.cs.v4.f32 [%0], {%1,%2,%3,%4};"
                 :: "l"(g), "f"(v.x), "f"(v.y), "f"(v.z), "f"(v.w) : "memory");
}
__device__ __forceinline__ unsigned pack_h2(float a, float b) {
    __half2 h = __floats2half2_rn(a, b);
    return *(unsigned*)&h;
}

// tf32 mma (projections)
__device__ __forceinline__ void mma8(float* d, const unsigned* a, const unsigned* b) {
    asm volatile(
        "mma.sync.aligned.m16n8k8.row.col.f32.tf32.tf32.f32 "
        "{%0,%1,%2,%3},{%4,%5,%6,%7},{%8,%9},{%0,%1,%2,%3};"
        : "+f"(d[0]), "+f"(d[1]), "+f"(d[2]), "+f"(d[3])
        : "r"(a[0]), "r"(a[1]), "r"(a[2]), "r"(a[3]), "r"(b[0]), "r"(b[1]));
}
// fp16 mma (attention)
__device__ __forceinline__ void mma16(float* d, const unsigned* a, const unsigned* b) {
    asm volatile(
        "mma.sync.aligned.m16n8k16.row.col.f32.f16.f16.f32 "
        "{%0,%1,%2,%3},{%4,%5,%6,%7},{%8,%9},{%0,%1,%2,%3};"
        : "+f"(d[0]), "+f"(d[1]), "+f"(d[2]), "+f"(d[3])
        : "r"(a[0]), "r"(a[1]), "r"(a[2]), "r"(a[3]), "r"(b[0]), "r"(b[1]));
}

// ---------------- pre-round weights to tf32 --------------------------------------
__global__ __launch_bounds__(256) void round_tf32(
    const float4* __restrict__ in, float4* __restrict__ out, int n4)
{
    int i = blockIdx.x * blockDim.x + threadIdx.x;
    if (i < n4) {
        float4 v = in[i];
        v.x = rndtf(v.x); v.y = rndtf(v.y); v.z = rndtf(v.z); v.w = rndtf(v.w);
        out[i] = v;
    }
}

// ---------------- transpose Vs[b][l][h*64+d] -> VsT[(b*16+h)*64+d][l] -------------
__global__ __launch_bounds__(256) void transpose_v(
    const __half* __restrict__ Vs, __half* __restrict__ VsT)
{
    __shared__ __half t[32][33];
    const int bh = blockIdx.z;
    const int b = bh >> 4, h = bh & 15;
    const int l0 = blockIdx.x * 32, d0 = blockIdx.y * 32;
    const int tx = threadIdx.x & 31, ty = threadIdx.x >> 5;   // 32 x 8
#pragma unroll
    for (int i = 0; i < 32; i += 8)
        t[ty + i][tx] = Vs[((size_t)b * L_ + l0 + ty + i) * HD_ + h * DK_ + d0 + tx];
    __syncthreads();
#pragma unroll
    for (int i = 0; i < 32; i += 8)
        VsT[((size_t)(bh * DK_ + d0 + ty + i)) * L_ + l0 + tx] = t[tx][ty + i];
}

// ================= TF32 SGEMM: C[M,N] = A[M,K] @ B[K,N] + bias ===================
// A raw fp32 (rounded in-register); B pre-rounded. Output fp16 (QKV) or fp32 (O).
template<bool HALF_OUT>
__global__ __launch_bounds__(256, 2) void sgemm_tf32(
    const float* __restrict__ A, const float* __restrict__ Bm,
    const float* __restrict__ bias, void* __restrict__ Cv,
    int M, int N, int K)
{
    __shared__ unsigned As[2][128][20];
    __shared__ unsigned Bs[2][16][136];
    const int tid  = threadIdx.x;
    const int lane = tid & 31, warp = tid >> 5;
    const int wr = warp >> 1, wc = warp & 1;
    const int gm = lane >> 2, kq = lane & 3;

    const float* Ab = A  + (size_t)(blockIdx.y * 128) * K;
    const float* Bb = Bm + blockIdx.x * 128;
    const int arow = tid >> 1,  acol = (tid & 1) * 8;
    const int brow = tid >> 4,  bcol = (tid & 15) * 8;

    float acc[2][8][4];
#pragma unroll
    for (int i = 0; i < 2; i++)
#pragma unroll
        for (int j = 0; j < 8; j++)
#pragma unroll
            for (int r = 0; r < 4; r++) acc[i][j][r] = 0.f;

    auto load = [&](int buf, int k0) {
        cp16(&As[buf][arow][acol],     Ab + (size_t)arow * K + k0 + acol);
        cp16(&As[buf][arow][acol + 4], Ab + (size_t)arow * K + k0 + acol + 4);
        cp16(&Bs[buf][brow][bcol],     Bb + (size_t)(k0 + brow) * N + bcol);
        cp16(&Bs[buf][brow][bcol + 4], Bb + (size_t)(k0 + brow) * N + bcol + 4);
    };

    load(0, 0); cpcommit();
    int buf = 0;
    for (int k0 = 0; k0 < K; k0 += 16) {
        if (k0 + 16 < K) { load(buf ^ 1, k0 + 16); cpcommit(); cpwait1(); }
        else             { cpwait0(); }
        __syncthreads();
#pragma unroll
        for (int kk = 0; kk < 16; kk += 8) {
            unsigned af[2][4], bf[8][2];
#pragma unroll
            for (int i = 0; i < 2; i++) {
                const int mb = wr * 32 + i * 16;
                af[i][0] = f2tf(__uint_as_float(As[buf][mb + gm    ][kk + kq]));
                af[i][1] = f2tf(__uint_as_float(As[buf][mb + gm + 8][kk + kq]));
                af[i][2] = f2tf(__uint_as_float(As[buf][mb + gm    ][kk + kq + 4]));
                af[i][3] = f2tf(__uint_as_float(As[buf][mb + gm + 8][kk + kq + 4]));
            }
#pragma unroll
            for (int j = 0; j < 8; j++) {
                const int nb = wc * 64 + j * 8;
                bf[j][0] = Bs[buf][kk + kq    ][nb + gm];
                bf[j][1] = Bs[buf][kk + kq + 4][nb + gm];
            }
#pragma unroll
            for (int i = 0; i < 2; i++)
#pragma unroll
                for (int j = 0; j < 8; j++) mma8(acc[i][j], af[i], bf[j]);
        }
        __syncthreads();
        buf ^= 1;
    }

#pragma unroll
    for (int i = 0; i < 2; i++)
#pragma unroll
        for (int j = 0; j < 8; j++) {
            const int row = blockIdx.y * 128 + wr * 32 + i * 16 + gm;
            const int col = blockIdx.x * 128 + wc * 64 + j * 8 + kq * 2;
            float2 bv = *(const float2*)(bias + col);
            float o0x = acc[i][j][0] + bv.x, o0y = acc[i][j][1] + bv.y;
            float o1x = acc[i][j][2] + bv.x, o1y = acc[i][j][3] + bv.y;
            if (HALF_OUT) {
                __half* C = (__half*)Cv;
                *(unsigned*)(C + (size_t)row * N + col)       = pack_h2(o0x, o0y);
                *(unsigned*)(C + (size_t)(row + 8) * N + col) = pack_h2(o1x, o1y);
            } else {
                float* C = (float*)Cv;
                *(float2*)(C + (size_t)row * N + col)       = make_float2(o0x, o0y);
                *(float2*)(C + (size_t)(row + 8) * N + col) = make_float2(o1x, o1y);
            }
        }
}

// ===== scores (fp16): per block = one (bh, q-tile); loops all 16 K-tiles ==========
// e = exp((Qh@Kh^T)/8), masked -> 0; writes e (fp32) to att and per-row invS.
#define SQS 36   // words per row: 32 data (64 halves) + 4 pad
#define SC_SMEM (3 * 128 * SQS * 4)   // Qt[128][36] + Kt[2][128][36]

__global__ __launch_bounds__(256, 2) void scores_fp16(
    const __half* __restrict__ Qs, const __half* __restrict__ Ks,
    const unsigned char* __restrict__ mask, float* __restrict__ att,
    float* __restrict__ invS)
{
    extern __shared__ unsigned sm[];
    unsigned (*Qt)[SQS]      = (unsigned(*)[SQS])sm;
    unsigned (*Kt)[128][SQS] = (unsigned(*)[128][SQS])(sm + 128 * SQS);
    __shared__ float ps[2][128];

    const int tid  = threadIdx.x;
    const int lane = tid & 31, warp = tid >> 5;
    const int wr = warp >> 1, wc = warp & 1;
    const int gm = lane >> 2, kq = lane & 3;
    const int bh = blockIdx.y;                  // b*16 + h
    const int b = bh >> 4, h = bh & 15;
    const int q0 = blockIdx.x * 128;

    const __half* Qb = Qs + (size_t)b * L_ * HD_ + (size_t)h * DK_;
    const __half* Kb = Ks + (size_t)b * L_ * HD_ + (size_t)h * DK_;
    const unsigned char* mb = mask + (size_t)b * L_ * L_;
    float* outb = att + (size_t)(h * B_ + b) * L_ * L_;

    const int lrow = tid >> 1;
    const int lwb = (tid & 1) * 16;   // word base in smem (16 words = 32 halves)
    const int lhb = (tid & 1) * 32;   // half base in gmem

    // group 0: Q tile + K tile 0
#pragma unroll
    for (int u = 0; u < 4; u++) {
        cp16(&Qt[lrow][lwb + u * 4],    Qb + (size_t)(q0 + lrow) * HD_ + lhb + u * 8);
        cp16(&Kt[0][lrow][lwb + u * 4], Kb + (size_t)lrow * HD_ + lhb + u * 8);
    }
    cpcommit();

    float sAcc0 = 0.f, sAcc1 = 0.f, sAcc2 = 0.f, sAcc3 = 0.f;

    for (int n = 0; n < 16; n++) {
        const int buf = n & 1;
        if (n + 1 < 16) {
#pragma unroll
            for (int u = 0; u < 4; u++)
                cp16(&Kt[buf ^ 1][lrow][lwb + u * 4],
                     Kb + (size_t)((n + 1) * 128 + lrow) * HD_ + lhb + u * 8);
            cpcommit(); cpwait1();
        } else cpwait0();
        __syncthreads();

        float acc[2][8][4];
#pragma unroll
        for (int i = 0; i < 2; i++)
#pragma unroll
            for (int j = 0; j < 8; j++)
#pragma unroll
                for (int r = 0; r < 4; r++) acc[i][j][r] = 0.f;

#pragma unroll
        for (int kw = 0; kw < 32; kw += 8) {    // 4 k16 steps (words)
            unsigned af[2][4], bf[8][2];
#pragma unroll
            for (int i = 0; i < 2; i++) {
                const int mbase = wr * 32 + i * 16;
                af[i][0] = Qt[mbase + gm    ][kw + kq];
                af[i][1] = Qt[mbase + gm + 8][kw + kq];
                af[i][2] = Qt[mbase + gm    ][kw + kq + 4];
                af[i][3] = Qt[mbase + gm + 8][kw + kq + 4];
            }
#pragma unroll
            for (int j = 0; j < 8; j++) {
                const int nb = wc * 64 + j * 8;
                bf[j][0] = Kt[buf][nb + gm][kw + kq];
                bf[j][1] = Kt[buf][nb + gm][kw + kq + 4];
            }
#pragma unroll
            for (int i = 0; i < 2; i++)
#pragma unroll
                for (int j = 0; j < 8; j++) mma16(acc[i][j], af[i], bf[j]);
        }

        // epilogue: mask, exp, write e (fp32), accumulate row sums
        const int n0 = n * 128;
#pragma unroll
        for (int i = 0; i < 2; i++) {
            float si0 = 0.f, si1 = 0.f;
#pragma unroll
            for (int j = 0; j < 8; j++) {
                const int q = q0 + wr * 32 + i * 16 + gm;
                const int k = n0 + wc * 64 + j * 8 + kq * 2;
                float e0 = mb[(size_t)q * L_ + k]           ? 0.f : __expf(acc[i][j][0] * 0.125f);
                float e1 = mb[(size_t)q * L_ + k + 1]       ? 0.f : __expf(acc[i][j][1] * 0.125f);
                float e2 = mb[(size_t)(q + 8) * L_ + k]     ? 0.f : __expf(acc[i][j][2] * 0.125f);
                float e3 = mb[(size_t)(q + 8) * L_ + k + 1] ? 0.f : __expf(acc[i][j][3] * 0.125f);
                si0 += e0 + e1;
                si1 += e2 + e3;
                *(float2*)(outb + (size_t)q * L_ + k)       = make_float2(e0, e1);
                *(float2*)(outb + (size_t)(q + 8) * L_ + k) = make_float2(e2, e3);
            }
            if (i == 0) { sAcc0 += si0; sAcc1 += si1; }
            else        { sAcc2 += si0; sAcc3 += si1; }
        }
        __syncthreads();
    }

#pragma unroll
    for (int i = 0; i < 2; i++) {
        float s0 = (i == 0) ? sAcc0 : sAcc2;
        float s1 = (i == 0) ? sAcc1 : sAcc3;
#pragma unroll
        for (int off = 1; off <= 2; off <<= 1) {
            s0 += __shfl_xor_sync(0xffffffffu, s0, off);
            s1 += __shfl_xor_sync(0xffffffffu, s1, off);
        }
        if (kq == 0) {
            const int r0 = wr * 32 + i * 16 + gm;
            ps[wc][r0] = s0;
            ps[wc][r0 + 8] = s1;
        }
    }
    __syncthreads();
    if (tid < 128)
        invS[(size_t)bh * L_ + q0 + tid] = 1.0f / (ps[0][tid] + ps[1][tid]);
}

// ====== fused PV (fp16): p = e*invS -> att fp32 + half2 smem; AO = p@V ===========
#define PRS 36   // raw e tile: 32 fp32 words + 4 pad
#define PHS 20   // packed p tile: 16 half2 words + 4 pad
#define VTS 20   // VsT tile: 16 half2 words + 4 pad
#define PV_SMEM ((2 * 128 * PRS + 2 * 128 * PHS + 2 * 64 * VTS) * 4)

__global__ __launch_bounds__(256, 2) void pv_fp16(
    float* __restrict__ att, const __half* __restrict__ VsT,
    const float* __restrict__ invS, float* __restrict__ AO)
{
    extern __shared__ unsigned sm[];
    unsigned (*PtR)[128][PRS] = (unsigned(*)[128][PRS])sm;
    unsigned (*PtH)[128][PHS] = (unsigned(*)[128][PHS])(sm + 2 * 128 * PRS);
    unsigned (*VtT)[64][VTS]  = (unsigned(*)[64][VTS])(sm + 2 * 128 * PRS + 2 * 128 * PHS);
    __shared__ float sInv[128];

    const int tid  = threadIdx.x;
    const int lane = tid & 31, warp = tid >> 5;
    const int wr = warp >> 1, wc = warp & 1;
    const int gm = lane >> 2, kq = lane & 3;
    const int bh = blockIdx.y;                  // b*16 + h
    const int b = bh >> 4, h = bh & 15;
    const int q0 = blockIdx.x * 128;

    float* Pb = att + (size_t)(h * B_ + b) * L_ * L_;
    const __half* Vb = VsT + (size_t)bh * DK_ * L_;
    const int prow = tid >> 1, pcb = (tid & 1) * 16;   // fp32 word base (16 floats)
    const int vrow = tid >> 2, vseg = tid & 3;

    float acc[2][4][4];
#pragma unroll
    for (int i = 0; i < 2; i++)
#pragma unroll
        for (int j = 0; j < 4; j++)
#pragma unroll
            for (int r = 0; r < 4; r++) acc[i][j][r] = 0.f;

    auto load = [&](int buf, int k0) {
#pragma unroll
        for (int u = 0; u < 4; u++)
            cp16(&PtR[buf][prow][pcb + u * 4],
                 Pb + (size_t)(q0 + prow) * L_ + k0 + pcb + u * 4);
        cp16(&VtT[buf][vrow][vseg * 4], Vb + (size_t)vrow * L_ + k0 + vseg * 8);
    };

    load(0, 0); cpcommit();

    if (tid < 128)
        sInv[tid] = invS[(size_t)bh * L_ + q0 + tid];

    int buf = 0;
    for (int k0 = 0; k0 < L_; k0 += 32) {
        if (k0 + 32 < L_) { load(buf ^ 1, k0 + 32); cpcommit(); cpwait1(); }
        else              { cpwait0(); }
        __syncthreads();

        // transform: p = e*invS -> fp32 gmem (streaming) + half2 smem
        {
            const float inv = sInv[prow];
            float* psm = (float*)&PtR[buf][prow][pcb];
            float* pgm = Pb + (size_t)(q0 + prow) * L_ + k0 + pcb;
            unsigned* ph = &PtH[buf][prow][(tid & 1) * 8];
#pragma unroll
            for (int u = 0; u < 4; u++) {
                float4 v = *(float4*)(psm + u * 4);
                v.x *= inv; v.y *= inv; v.z *= inv; v.w *= inv;
                stg_cs4(pgm + u * 4, v);
                ph[u * 2]     = pack_h2(v.x, v.y);
                ph[u * 2 + 1] = pack_h2(v.z, v.w);
            }
        }
        __syncthreads();

#pragma unroll
        for (int kw = 0; kw < 16; kw += 8) {    // 2 k16 steps
            unsigned af[2][4], bf[4][2];
#pragma unroll
            for (int i = 0; i < 2; i++) {
                const int mbase = wr * 32 + i * 16;
                af[i][0] = PtH[buf][mbase + gm    ][kw + kq];
                af[i][1] = PtH[buf][mbase + gm + 8][kw + kq];
                af[i][2] = PtH[buf][mbase + gm    ][kw + kq + 4];
                af[i][3] = PtH[buf][mbase + gm + 8][kw + kq + 4];
            }
#pragma unroll
            for (int j = 0; j < 4; j++) {
                const int nb = wc * 32 + j * 8;
                bf[j][0] = VtT[buf][nb + gm][kw + kq];
                bf[j][1] = VtT[buf][nb + gm][kw + kq + 4];
            }
#pragma unroll
            for (int i = 0; i < 2; i++)
#pragma unroll
                for (int j = 0; j < 4; j++) mma16(acc[i][j], af[i], bf[j]);
        }
        __syncthreads();
        buf ^= 1;
    }

#pragma unroll
    for (int i = 0; i < 2; i++)
#pragma unroll
        for (int j = 0; j < 4; j++) {
            const int q = q0 + wr * 32 + i * 16 + gm;
            const int col = wc * 32 + j * 8 + kq * 2;
            *(float2*)(AO + (size_t)(b * L_ + q) * HD_ + h * DK_ + col) =
                make_float2(acc[i][j][0], acc[i][j][1]);
            *(float2*)(AO + (size_t)(b * L_ + q + 8) * HD_ + h * DK_ + col) =
                make_float2(acc[i][j][2], acc[i][j][3]);
        }
}

// ---------------- residual + LayerNorm: y = LN(X + Q)*gamma + beta ---------------
__global__ __launch_bounds__(256) void ln_kernel(
    const float* __restrict__ X, const float* __restrict__ Qin,
    const float* __restrict__ gamma, const float* __restrict__ beta,
    float* __restrict__ y)
{
    __shared__ float red[8];
    const int row = blockIdx.x;
    const int tid = threadIdx.x;
    const float* xr = X + (size_t)row * DX_;
    const float* qr = Qin + (size_t)row * DX_;

    float x[4];
#pragma unroll
    for (int i = 0; i < 4; i++) x[i] = xr[tid + 256 * i] + qr[tid + 256 * i];

    float s = x[0] + x[1] + x[2] + x[3];
#pragma unroll
    for (int o = 16; o; o >>= 1) s += __shfl_xor_sync(0xffffffffu, s, o);
    if ((tid & 31) == 0) red[tid >> 5] = s;
    __syncthreads();
    s = red[0];
#pragma unroll
    for (int w = 1; w < 8; w++) s += red[w];
    const float mu = s * (1.0f / DX_);
    __syncthreads();

    float vs = 0.f;
#pragma unroll
    for (int i = 0; i < 4; i++) { float d = x[i] - mu; vs += d * d; }
#pragma unroll
    for (int o = 16; o; o >>= 1) vs += __shfl_xor_sync(0xffffffffu, vs, o);
    if ((tid & 31) == 0) red[tid >> 5] = vs;
    __syncthreads();
    vs = red[0];
#pragma unroll
    for (int w = 1; w < 8; w++) vs += red[w];
    const float var = vs * (1.0f / DX_);
    const float rs = rsqrtf(var + EPS_);

#pragma unroll
    for (int i = 0; i < 4; i++) {
        const int c = tid + 256 * i;
        y[(size_t)row * DX_ + c] = (x[i] - mu) * rs * gamma[c] + beta[c];
    }
}

// --------------------------------- launch ---------------------------------------
extern "C" void kernel_launch(void* const* d_in, const int* in_sizes, int n_in,
                              void* d_out, int out_size)
{
    const float* Q  = (const float*)d_in[0];
    const float* K  = (const float*)d_in[1];
    const float* V  = (const float*)d_in[2];
    const unsigned char* mask = (const unsigned char*)d_in[3];
    const float* Wq = (const float*)d_in[4];
    const float* bq = (const float*)d_in[5];
    const float* Wk = (const float*)d_in[6];
    const float* bk = (const float*)d_in[7];
    const float* Wv = (const float*)d_in[8];
    const float* bv = (const float*)d_in[9];
    const float* Wo = (const float*)d_in[10];
    const float* bo = (const float*)d_in[11];
    const float* gamma = (const float*)d_in[12];
    const float* beta  = (const float*)d_in[13];

    float* y   = (float*)d_out;
    float* att = (float*)d_out + (size_t)B_ * L_ * DX_;

    static __half *pQs=nullptr,*pKs=nullptr,*pVs=nullptr,*pVsT=nullptr;
    static float *pAO=nullptr,*pX=nullptr;
    static float *prWq=nullptr,*prWk=nullptr,*prWv=nullptr,*prWo=nullptr;
    static float *pInv=nullptr;
    static cudaStream_t s1, s2, s3;
    static cudaEvent_t evS, ev1, ev2, ev3;
    if (!pQs) {
        cudaGetSymbolAddress((void**)&pQs, g_Qs);
        cudaGetSymbolAddress((void**)&pKs, g_Ks);
        cudaGetSymbolAddress((void**)&pVs, g_Vs);
        cudaGetSymbolAddress((void**)&pVsT, g_VsT);
        cudaGetSymbolAddress((void**)&pAO, g_AO);
        cudaGetSymbolAddress((void**)&pX,  g_X);
        cudaGetSymbolAddress((void**)&prWq, g_rWq);
        cudaGetSymbolAddress((void**)&prWk, g_rWk);
        cudaGetSymbolAddress((void**)&prWv, g_rWv);
        cudaGetSymbolAddress((void**)&prWo, g_rWo);
        cudaGetSymbolAddress((void**)&pInv, g_invS);
        cudaFuncSetAttribute(scores_fp16, cudaFuncAttributeMaxDynamicSharedMemorySize,
                             SC_SMEM);
        cudaFuncSetAttribute(pv_fp16, cudaFuncAttributeMaxDynamicSharedMemorySize,
                             PV_SMEM);
        cudaStreamCreateWithFlags(&s1, cudaStreamNonBlocking);
        cudaStreamCreateWithFlags(&s2, cudaStreamNonBlocking);
        cudaStreamCreateWithFlags(&s3, cudaStreamNonBlocking);
        cudaEventCreateWithFlags(&evS, cudaEventDisableTiming);
        cudaEventCreateWithFlags(&ev1, cudaEventDisableTiming);
        cudaEventCreateWithFlags(&ev2, cudaEventDisableTiming);
        cudaEventCreateWithFlags(&ev3, cudaEventDisableTiming);
    }

    const int nW = DX_ * HD_ / 4;                   // float4 count for a weight matrix
    const dim3 gProj(HD_ / 128, (B_ * L_) / 128);   // (8, 64)

    // fork
    cudaEventRecord(evS, 0);
    cudaStreamWaitEvent(s1, evS, 0);
    cudaStreamWaitEvent(s2, evS, 0);
    cudaStreamWaitEvent(s3, evS, 0);

    // s1: K chain (joins before scores)
    round_tf32<<<nW / 256, 256, 0, s1>>>((const float4*)Wk, (float4*)prWk, nW);
    sgemm_tf32<true><<<gProj, 256, 0, s1>>>(K, prWk, bk, pKs, B_ * L_, HD_, DX_);
    cudaEventRecord(ev1, s1);

    // s2: V chain + transpose (joins before pv — overlaps scores)
    round_tf32<<<nW / 256, 256, 0, s2>>>((const float4*)Wv, (float4*)prWv, nW);
    sgemm_tf32<true><<<gProj, 256, 0, s2>>>(V, prWv, bv, pVs, B_ * L_, HD_, DX_);
    transpose_v<<<dim3(L_ / 32, DK_ / 32, B_ * H_), 256, 0, s2>>>(pVs, pVsT);
    cudaEventRecord(ev2, s2);

    // s3: Wo prep (joins before output projection)
    round_tf32<<<nW / 256, 256, 0, s3>>>((const float4*)Wo, (float4*)prWo, nW);
    cudaEventRecord(ev3, s3);

    // main: Q chain -> attention
    round_tf32<<<nW / 256, 256>>>((const float4*)Wq, (float4*)prWq, nW);
    sgemm_tf32<true><<<gProj, 256>>>(Q, prWq, bq, pQs, B_ * L_, HD_, DX_);

    cudaStreamWaitEvent(0, ev1, 0);
    scores_fp16<<<dim3(L_ / 128, B_ * H_), 256, SC_SMEM>>>(
        pQs, pKs, mask, att, pInv);

    cudaStreamWaitEvent(0, ev2, 0);
    pv_fp16<<<dim3(L_ / 128, B_ * H_), 256, PV_SMEM>>>(att, pVsT, pInv, pAO);

    cudaStreamWaitEvent(0, ev3, 0);
    sgemm_tf32<false><<<gProj, 256>>>(pAO, prWo, bo, pX, B_ * L_, DX_, HD_);
    ln_kernel<<<B_ * L_, 256>>>(pX, Q, gamma, beta, y);
}